// round 7
// baseline (speedup 1.0000x reference)
#include <cuda_runtime.h>
#include <cuda_fp16.h>
#include <cstdint>

// ============================================================================
// helpers
// ============================================================================
__device__ __forceinline__ uint32_t smem_u32(const void* p) {
    uint32_t a;
    asm("{ .reg .u64 t; cvta.to.shared.u64 t, %1; cvt.u32.u64 %0, t; }" : "=r"(a) : "l"(p));
    return a;
}
__host__ __device__ __forceinline__ uint32_t swz128(uint32_t off) {
    return off ^ ((off >> 3) & 0x70);
}
__device__ __forceinline__ void ldsm4(uint32_t r[4], uint32_t addr) {
    asm volatile("ldmatrix.sync.aligned.m8n8.x4.shared.b16 {%0,%1,%2,%3}, [%4];"
                 : "=r"(r[0]), "=r"(r[1]), "=r"(r[2]), "=r"(r[3]) : "r"(addr));
}
__device__ __forceinline__ void mma16816(float d[4], const uint32_t a[4], uint32_t b0, uint32_t b1) {
    asm volatile("mma.sync.aligned.m16n8k16.row.col.f32.f16.f16.f32 "
                 "{%0,%1,%2,%3}, {%4,%5,%6,%7}, {%8,%9}, {%0,%1,%2,%3};"
                 : "+f"(d[0]), "+f"(d[1]), "+f"(d[2]), "+f"(d[3])
                 : "r"(a[0]), "r"(a[1]), "r"(a[2]), "r"(a[3]), "r"(b0), "r"(b1));
}
__device__ __forceinline__ void cpa8(uint32_t dst, const void* src) {
    asm volatile("cp.async.ca.shared.global [%0], [%1], 8;" :: "r"(dst), "l"(src));
}
__device__ __forceinline__ void cpa16(uint32_t dst, const void* src) {
    asm volatile("cp.async.cg.shared.global [%0], [%1], 16;" :: "r"(dst), "l"(src));
}
#define CP_COMMIT() asm volatile("cp.async.commit_group;" ::: "memory")
#define CP_WAIT0()  asm volatile("cp.async.wait_group 0;" ::: "memory")

// ============================================================================
// smem layout (per CTA, 91,136 B; 2 CTAs/SM = 178 KB < 228 KB)
// ============================================================================
static constexpr int SMEM_AHI  = 0;        // 16 KB: A_hi 128x64 fp16, SW128 rows
static constexpr int SMEM_ALO  = 16384;    // 16 KB: A_lo
static constexpr int SMEM_BHI  = 32768;    // 24 KB: B_hi 192x64 fp16, SW128 rows
static constexpr int SMEM_RAW  = 57344;    // 32 KB: raw fp32 A staging (cp.async)
static constexpr int OFF_PSUM  = 57344;    // reuse raw region post-compute
static constexpr int OFF_PSQ   = 61440;
static constexpr int OFF_STAT  = 90112;    // 1 KB
static constexpr int SMEM_TOTAL = 91136;

// ---------------- device scratch ----------------
__device__ float  g_s1[192];
__device__ float  g_s2[192];
__device__ float4 g_Bh[12 * 1536];   // 12 chunks x 24KB, pre-swizzled tile layout (fp16 hi)

// ---------------- prep kernel: B plane + s1/s2 ----------------
__global__ void k_prep(const float* __restrict__ gamma, const float* __restrict__ beta,
                       const float* __restrict__ w) {
    if (blockIdx.x < 576) {
        int t = blockIdx.x * 256 + threadIdx.x;
        int k = t / 192;       // original k = p*96 + c
        int n = t % 192;
        int p = k / 96, c = k % 96;
        float val = gamma[k] * w[k * 192 + n];
        int chunk = c >> 3;
        int kl = (c & 7) * 8 + p;              // k-hat within chunk
        uint32_t off = swz128((uint32_t)(n * 128 + kl * 2));
        *(__half*)((unsigned char*)g_Bh + chunk * 24576 + off) = __float2half_rn(val);
    } else {
        int n = blockIdx.x - 576;
        __shared__ float s1s[256], s2s[256];
        float s1 = 0.f, s2 = 0.f;
        for (int k = threadIdx.x; k < 768; k += 256) {
            float wv = w[k * 192 + n];
            s1 += gamma[k] * wv;
            s2 += beta[k] * wv;
        }
        s1s[threadIdx.x] = s1; s2s[threadIdx.x] = s2;
        __syncthreads();
        for (int off = 128; off > 0; off >>= 1) {
            if (threadIdx.x < off) { s1s[threadIdx.x] += s1s[threadIdx.x + off]; s2s[threadIdx.x] += s2s[threadIdx.x + off]; }
            __syncthreads();
        }
        if (threadIdx.x == 0) { g_s1[n] = s1s[0]; g_s2[n] = s2s[0]; }
    }
}

// ---------------- main fused kernel ----------------
__global__ void __launch_bounds__(256, 2) k_main(const float* __restrict__ x,
                                                 float* __restrict__ out) {
    extern __shared__ unsigned char smem[];
    const uint32_t sb  = smem_u32(smem);
    const int tid  = threadIdx.x;
    const int lane = tid & 31;
    const int wrp  = tid >> 5;
    const int wm   = wrp & 3;       // M quadrant (32 rows)
    const int wn   = wrp >> 2;      // N half (96 cols)

    // block coords: 128 consecutive m
    const int m0 = blockIdx.x * 128;
    const int b  = m0 >> 14;
    const int d  = (m0 >> 10) & 15;
    const int h0 = (m0 >> 5) & 31;     // multiple of 4
    const int idx = tid >> 5;          // c_local 0..7 (loader role)
    const int w   = tid & 31;

    const float2* x2 = (const float2*)x;
    const size_t baseIdx = ((size_t)(b * 96 + idx) * 32 + 2 * d) * 2048 + (size_t)(2 * h0) * 32 + w;

    // ldmatrix lane address components
    const int g  = lane >> 3, rl = lane & 7;
    const int aRowLane = ((g & 1) << 3) + rl;
    const int aKLane   = (g >> 1) << 4;
    const int bRowLane = ((g >> 1) << 3) + rl;
    const int bKLane   = (g & 1) << 4;

    float acc[2][12][4];
#pragma unroll
    for (int mt = 0; mt < 2; mt++)
#pragma unroll
        for (int ng = 0; ng < 12; ng++)
#pragma unroll
            for (int r = 0; r < 4; r++) acc[mt][ng][r] = 0.f;

    float sA[4] = {0.f, 0.f, 0.f, 0.f};
    float sQ[4] = {0.f, 0.f, 0.f, 0.f};

    const float2* rawf2 = (const float2*)(smem + SMEM_RAW);

    // ---- prologue: stage raw A chunk 0 ----
#pragma unroll
    for (int i = 0; i < 16; i++)
        cpa8(sb + SMEM_RAW + (uint32_t)(i * 256 + tid) * 8,
             x2 + baseIdx + (size_t)((i >> 3) * 2048 + ((i >> 1) & 3) * 64 + (i & 1) * 32));
    CP_COMMIT();

    for (int t = 0; t < 12; t++) {
        CP_WAIT0();            // raw(t) staged
        __syncthreads();       // compute(t-1) done -> A/B tiles reusable

        // B_hi(t): cp.async from pre-swizzled gmem (L2-hot), latency hidden by convert below
        {
            const float4* bsrc = g_Bh + (size_t)t * 1536 + tid;
#pragma unroll
            for (int j = 0; j < 6; j++)
                cpa16(sb + SMEM_BHI + (uint32_t)(j * 256 + tid) * 16, bsrc + j * 256);
            CP_COMMIT();
        }

        // ---- convert raw(t): fp32 -> fp16 hi/lo, stats, STS ----
#pragma unroll
        for (int i = 0; i < 16; i++) {
            float2 v = rawf2[i * 256 + tid];
            const int dz = i >> 3, hout = (i >> 1) & 3, hy = i & 1;
            const int kl = idx * 8 + dz * 4 + hy * 2;
            const int ml = hout * 32 + w;
            __half2 hi2 = __float22half2_rn(v);
            float2 hf = __half22float2(hi2);
            __half2 lo2 = __float22half2_rn(make_float2(v.x - hf.x, v.y - hf.y));
            uint32_t off = swz128((uint32_t)(ml * 128 + kl * 2));
            *(uint32_t*)(smem + SMEM_AHI + off) = *(uint32_t*)&hi2;
            *(uint32_t*)(smem + SMEM_ALO + off) = *(uint32_t*)&lo2;
            sA[hout] += v.x + v.y;
            sQ[hout] = fmaf(v.x, v.x, fmaf(v.y, v.y, sQ[hout]));
        }
        CP_WAIT0();            // B_hi(t) staged
        __syncthreads();

        // stage raw(t+1) during compute
        if (t < 11) {
            const size_t cb = baseIdx + (size_t)(t + 1) * 524288;
#pragma unroll
            for (int i = 0; i < 16; i++)
                cpa8(sb + SMEM_RAW + (uint32_t)(i * 256 + tid) * 8,
                     x2 + cb + (size_t)((i >> 3) * 2048 + ((i >> 1) & 3) * 64 + (i & 1) * 32));
            CP_COMMIT();
        }

        // ---- compute: 4 k16-steps x 2 terms ----
#pragma unroll
        for (int ks = 0; ks < 4; ks++) {
            uint32_t ahi[2][4], alo[2][4];
#pragma unroll
            for (int mt = 0; mt < 2; mt++) {
                uint32_t rowoff = (uint32_t)((wm * 32 + mt * 16 + aRowLane) * 128 + ks * 32 + aKLane);
                ldsm4(ahi[mt], sb + SMEM_AHI + swz128(rowoff));
                ldsm4(alo[mt], sb + SMEM_ALO + swz128(rowoff));
            }
#pragma unroll
            for (int ng2 = 0; ng2 < 6; ng2++) {
                uint32_t boff = (uint32_t)((wn * 96 + ng2 * 16 + bRowLane) * 128 + ks * 32 + bKLane);
                uint32_t bb[4];
                ldsm4(bb, sb + SMEM_BHI + swz128(boff));
                mma16816(acc[0][2 * ng2],     ahi[0], bb[0], bb[1]);
                mma16816(acc[1][2 * ng2],     ahi[1], bb[0], bb[1]);
                mma16816(acc[0][2 * ng2 + 1], ahi[0], bb[2], bb[3]);
                mma16816(acc[1][2 * ng2 + 1], ahi[1], bb[2], bb[3]);
                mma16816(acc[0][2 * ng2],     alo[0], bb[0], bb[1]);
                mma16816(acc[1][2 * ng2],     alo[1], bb[0], bb[1]);
                mma16816(acc[0][2 * ng2 + 1], alo[0], bb[2], bb[3]);
                mma16816(acc[1][2 * ng2 + 1], alo[1], bb[2], bb[3]);
            }
        }
    }
    __syncthreads();

    // ---- LayerNorm stats reduce ----
    float* psum = (float*)(smem + OFF_PSUM);
    float* psq  = (float*)(smem + OFF_PSQ);
#pragma unroll
    for (int hout = 0; hout < 4; hout++) {
        psum[idx * 128 + hout * 32 + w] = sA[hout];
        psq[idx * 128 + hout * 32 + w]  = sQ[hout];
    }
    __syncthreads();
    float* stat = (float*)(smem + OFF_STAT);
    if (tid < 128) {
        float S = 0.f, Q = 0.f;
#pragma unroll
        for (int r = 0; r < 8; r++) { S += psum[r * 128 + tid]; Q += psq[r * 128 + tid]; }
        float mu  = S * (1.0f / 768.0f);
        float var = Q * (1.0f / 768.0f) - mu * mu;
        float rs  = rsqrtf(var + 1e-5f);
        stat[tid]       = rs;
        stat[128 + tid] = -rs * mu;
    }
    __syncthreads();

    // ---- epilogue: LN affine + transposed writeback (two n-halves of 96) ----
    float* sbuf = (float*)smem;   // 96 x 128 floats = 48 KB (overlaps tiles)
    const int sp0 = (m0 & 16383);
    for (int h = 0; h < 2; h++) {
        if (wn == h) {
#pragma unroll
            for (int mt = 0; mt < 2; mt++)
#pragma unroll
                for (int ng = 0; ng < 12; ng++)
#pragma unroll
                    for (int r = 0; r < 4; r++) {
                        int m_loc = wm * 32 + mt * 16 + (lane >> 2) + ((r >> 1) << 3);
                        int n_loc = ng * 8 + ((lane & 3) << 1) + (r & 1);
                        int n_glb = h * 96 + n_loc;
                        float v = fmaf(stat[m_loc], acc[mt][ng][r],
                                       fmaf(stat[128 + m_loc], __ldg(&g_s1[n_glb]), __ldg(&g_s2[n_glb])));
                        sbuf[n_loc * 128 + m_loc] = v;
                    }
        }
        __syncthreads();
#pragma unroll
        for (int r = 0; r < 48; r++) {
            int e  = r * 256 + tid;
            int nl = e >> 7;
            int ml = e & 127;
            int n  = h * 96 + nl;
            out[(size_t)(b * 192 + n) * 16384 + sp0 + ml] = sbuf[e];
        }
        if (h == 0) __syncthreads();
    }
}

// ---------------- launch ----------------
extern "C" void kernel_launch(void* const* d_in, const int* in_sizes, int n_in,
                              void* d_out, int out_size) {
    const float* x     = (const float*)d_in[0];
    const float* gamma = (const float*)d_in[1];
    const float* beta  = (const float*)d_in[2];
    const float* w_red = (const float*)d_in[3];
    float* out = (float*)d_out;

    cudaFuncSetAttribute(k_main, cudaFuncAttributeMaxDynamicSharedMemorySize, SMEM_TOTAL);

    k_prep<<<768, 256>>>(gamma, beta, w_red);
    k_main<<<256, 256, SMEM_TOTAL>>>(x, out);
}

// round 8
// speedup vs baseline: 1.3883x; 1.3883x over previous
#include <cuda_runtime.h>
#include <cuda_fp16.h>
#include <cstdint>

// ============================================================================
// helpers
// ============================================================================
__device__ __forceinline__ uint32_t smem_u32(const void* p) {
    uint32_t a;
    asm("{ .reg .u64 t; cvta.to.shared.u64 t, %1; cvt.u32.u64 %0, t; }" : "=r"(a) : "l"(p));
    return a;
}
__host__ __device__ __forceinline__ uint32_t swz128(uint32_t off) {
    return off ^ ((off >> 3) & 0x70);
}
__device__ __forceinline__ void ldsm4(uint32_t r[4], uint32_t addr) {
    asm volatile("ldmatrix.sync.aligned.m8n8.x4.shared.b16 {%0,%1,%2,%3}, [%4];"
                 : "=r"(r[0]), "=r"(r[1]), "=r"(r[2]), "=r"(r[3]) : "r"(addr));
}
__device__ __forceinline__ void mma16816(float d[4], const uint32_t a[4], uint32_t b0, uint32_t b1) {
    asm volatile("mma.sync.aligned.m16n8k16.row.col.f32.f16.f16.f32 "
                 "{%0,%1,%2,%3}, {%4,%5,%6,%7}, {%8,%9}, {%0,%1,%2,%3};"
                 : "+f"(d[0]), "+f"(d[1]), "+f"(d[2]), "+f"(d[3])
                 : "r"(a[0]), "r"(a[1]), "r"(a[2]), "r"(a[3]), "r"(b0), "r"(b1));
}
__device__ __forceinline__ void cpa16(uint32_t dst, const void* src) {
    asm volatile("cp.async.cg.shared.global [%0], [%1], 16;" :: "r"(dst), "l"(src));
}
#define CP_COMMIT() asm volatile("cp.async.commit_group;" ::: "memory")
#define CP_WAIT0()  asm volatile("cp.async.wait_group 0;" ::: "memory")

// ============================================================================
// smem layout (per CTA 82,944 B; 2 CTAs/SM = 165,888 B < 228 KB)
// ============================================================================
static constexpr int SMEM_AHI  = 0;        // 16 KB: A_hi 128x64 fp16, SW128 rows
static constexpr int SMEM_ALO  = 16384;    // 16 KB: A_lo
static constexpr int SMEM_B0   = 32768;    // 24 KB: B_hi buffer 0
static constexpr int SMEM_B1   = 57344;    // 24 KB: B_hi buffer 1
static constexpr int OFF_PSUM  = 32768;    // reuse B0 after compute
static constexpr int OFF_PSQ   = 36864;
static constexpr int OFF_STAT  = 81920;    // 1 KB
static constexpr int SMEM_TOTAL = 82944;

// ---------------- device scratch ----------------
__device__ float  g_s1[192];
__device__ float  g_s2[192];
__device__ float4 g_Bh[12 * 1536];   // 12 chunks x 24KB, pre-swizzled tile layout (fp16 hi)

// ---------------- prep kernel: B plane + s1/s2 ----------------
__global__ void k_prep(const float* __restrict__ gamma, const float* __restrict__ beta,
                       const float* __restrict__ w) {
    if (blockIdx.x < 576) {
        int t = blockIdx.x * 256 + threadIdx.x;
        int k = t / 192;       // original k = p*96 + c
        int n = t % 192;
        int p = k / 96, c = k % 96;
        float val = gamma[k] * w[k * 192 + n];
        int chunk = c >> 3;
        int kl = (c & 7) * 8 + p;              // k-hat within chunk
        uint32_t off = swz128((uint32_t)(n * 128 + kl * 2));
        *(__half*)((unsigned char*)g_Bh + chunk * 24576 + off) = __float2half_rn(val);
    } else {
        int n = blockIdx.x - 576;
        __shared__ float s1s[256], s2s[256];
        float s1 = 0.f, s2 = 0.f;
        for (int k = threadIdx.x; k < 768; k += 256) {
            float wv = w[k * 192 + n];
            s1 += gamma[k] * wv;
            s2 += beta[k] * wv;
        }
        s1s[threadIdx.x] = s1; s2s[threadIdx.x] = s2;
        __syncthreads();
        for (int off = 128; off > 0; off >>= 1) {
            if (threadIdx.x < off) { s1s[threadIdx.x] += s1s[threadIdx.x + off]; s2s[threadIdx.x] += s2s[threadIdx.x + off]; }
            __syncthreads();
        }
        if (threadIdx.x == 0) { g_s1[n] = s1s[0]; g_s2[n] = s2s[0]; }
    }
}

// ---------------- main fused kernel ----------------
__global__ void __launch_bounds__(256, 2) k_main(const float* __restrict__ x,
                                                 float* __restrict__ out) {
    extern __shared__ unsigned char smem[];
    const uint32_t sb  = smem_u32(smem);
    const int tid  = threadIdx.x;
    const int lane = tid & 31;
    const int wrp  = tid >> 5;
    const int wm   = wrp & 3;       // M quadrant (32 rows)
    const int wn   = wrp >> 2;      // N half (96 cols)

    // block coords: 128 consecutive m
    const int m0 = blockIdx.x * 128;
    const int b  = m0 >> 14;
    const int d  = (m0 >> 10) & 15;
    const int h0 = (m0 >> 5) & 31;     // multiple of 4
    const int idx = tid >> 5;          // c_local 0..7 (loader role)
    const int w   = tid & 31;

    const float2* x2 = (const float2*)x;
    const size_t baseIdx = ((size_t)(b * 96 + idx) * 32 + 2 * d) * 2048 + (size_t)(2 * h0) * 32 + w;

    // ldmatrix lane address components
    const int g  = lane >> 3, rl = lane & 7;
    const int aRowLane = ((g & 1) << 3) + rl;
    const int aKLane   = (g >> 1) << 4;
    const int bRowLane = ((g >> 1) << 3) + rl;
    const int bKLane   = (g & 1) << 4;

    float acc[2][12][4];
#pragma unroll
    for (int mt = 0; mt < 2; mt++)
#pragma unroll
        for (int ng = 0; ng < 12; ng++)
#pragma unroll
            for (int r = 0; r < 4; r++) acc[mt][ng][r] = 0.f;

    float sA[4] = {0.f, 0.f, 0.f, 0.f};
    float sQ[4] = {0.f, 0.f, 0.f, 0.f};

    float2 aPf[16];
    // ---- prologue: prefetch A chunk 0 into regs; stream B(0) via cp.async ----
#pragma unroll
    for (int i = 0; i < 16; i++)
        aPf[i] = x2[baseIdx + (size_t)((i >> 3) * 2048 + ((i >> 1) & 3) * 64 + (i & 1) * 32)];
    {
        const float4* bsrc = g_Bh + tid;
#pragma unroll
        for (int j = 0; j < 6; j++)
            cpa16(sb + SMEM_B0 + (uint32_t)(j * 256 + tid) * 16, bsrc + j * 256);
        CP_COMMIT();
    }

    for (int t = 0; t < 12; t++) {
        if (t) __syncthreads();   // compute(t-1) done -> A tiles reusable

        // ---- convert A(t) from regs: fp32 -> fp16 hi/lo, stats, STS ----
#pragma unroll
        for (int i = 0; i < 16; i++) {
            float2 v = aPf[i];
            const int dz = i >> 3, hout = (i >> 1) & 3, hy = i & 1;
            const int kl = idx * 8 + dz * 4 + hy * 2;
            const int ml = hout * 32 + w;
            __half2 hi2 = __float22half2_rn(v);
            float2 hf = __half22float2(hi2);
            __half2 lo2 = __float22half2_rn(make_float2(v.x - hf.x, v.y - hf.y));
            uint32_t off = swz128((uint32_t)(ml * 128 + kl * 2));
            *(uint32_t*)(smem + SMEM_AHI + off) = *(uint32_t*)&hi2;
            *(uint32_t*)(smem + SMEM_ALO + off) = *(uint32_t*)&lo2;
            sA[hout] += v.x + v.y;
            sQ[hout] = fmaf(v.x, v.x, fmaf(v.y, v.y, sQ[hout]));
        }
        CP_WAIT0();            // B(t) staged
        __syncthreads();

        // ---- stream B(t+1) into other buffer; prefetch A(t+1) into regs ----
        if (t < 11) {
            const float4* bsrc = g_Bh + (size_t)(t + 1) * 1536 + tid;
            uint32_t bdst = sb + ((t + 1) & 1 ? SMEM_B1 : SMEM_B0);
#pragma unroll
            for (int j = 0; j < 6; j++)
                cpa16(bdst + (uint32_t)(j * 256 + tid) * 16, bsrc + j * 256);
            CP_COMMIT();
            const size_t cb = baseIdx + (size_t)(t + 1) * 524288;
#pragma unroll
            for (int i = 0; i < 16; i++)
                aPf[i] = x2[cb + (size_t)((i >> 3) * 2048 + ((i >> 1) & 3) * 64 + (i & 1) * 32)];
        }

        // ---- compute on B buffer t&1: 4 k16-steps x 2 terms ----
        const uint32_t bbase = sb + (t & 1 ? SMEM_B1 : SMEM_B0);
#pragma unroll
        for (int ks = 0; ks < 4; ks++) {
            uint32_t ahi[2][4], alo[2][4];
#pragma unroll
            for (int mt = 0; mt < 2; mt++) {
                uint32_t rowoff = (uint32_t)((wm * 32 + mt * 16 + aRowLane) * 128 + ks * 32 + aKLane);
                ldsm4(ahi[mt], sb + SMEM_AHI + swz128(rowoff));
                ldsm4(alo[mt], sb + SMEM_ALO + swz128(rowoff));
            }
#pragma unroll
            for (int ng2 = 0; ng2 < 6; ng2++) {
                uint32_t boff = (uint32_t)((wn * 96 + ng2 * 16 + bRowLane) * 128 + ks * 32 + bKLane);
                uint32_t bb[4];
                ldsm4(bb, bbase + swz128(boff));
                mma16816(acc[0][2 * ng2],     ahi[0], bb[0], bb[1]);
                mma16816(acc[1][2 * ng2],     ahi[1], bb[0], bb[1]);
                mma16816(acc[0][2 * ng2 + 1], ahi[0], bb[2], bb[3]);
                mma16816(acc[1][2 * ng2 + 1], ahi[1], bb[2], bb[3]);
                mma16816(acc[0][2 * ng2],     alo[0], bb[0], bb[1]);
                mma16816(acc[1][2 * ng2],     alo[1], bb[0], bb[1]);
                mma16816(acc[0][2 * ng2 + 1], alo[0], bb[2], bb[3]);
                mma16816(acc[1][2 * ng2 + 1], alo[1], bb[2], bb[3]);
            }
        }
    }
    __syncthreads();

    // ---- LayerNorm stats reduce ----
    float* psum = (float*)(smem + OFF_PSUM);
    float* psq  = (float*)(smem + OFF_PSQ);
#pragma unroll
    for (int hout = 0; hout < 4; hout++) {
        psum[idx * 128 + hout * 32 + w] = sA[hout];
        psq[idx * 128 + hout * 32 + w]  = sQ[hout];
    }
    __syncthreads();
    float* stat = (float*)(smem + OFF_STAT);
    if (tid < 128) {
        float S = 0.f, Q = 0.f;
#pragma unroll
        for (int r = 0; r < 8; r++) { S += psum[r * 128 + tid]; Q += psq[r * 128 + tid]; }
        float mu  = S * (1.0f / 768.0f);
        float var = Q * (1.0f / 768.0f) - mu * mu;
        float rs  = rsqrtf(var + 1e-5f);
        stat[tid]       = rs;
        stat[128 + tid] = -rs * mu;
    }
    __syncthreads();

    // ---- epilogue: LN affine + transposed writeback (two n-halves of 96) ----
    float* sbuf = (float*)smem;   // 96 x 128 floats = 48 KB (overlaps tiles)
    const int sp0 = (m0 & 16383);
    for (int h = 0; h < 2; h++) {
        if (wn == h) {
#pragma unroll
            for (int mt = 0; mt < 2; mt++)
#pragma unroll
                for (int ng = 0; ng < 12; ng++)
#pragma unroll
                    for (int r = 0; r < 4; r++) {
                        int m_loc = wm * 32 + mt * 16 + (lane >> 2) + ((r >> 1) << 3);
                        int n_loc = ng * 8 + ((lane & 3) << 1) + (r & 1);
                        int n_glb = h * 96 + n_loc;
                        float v = fmaf(stat[m_loc], acc[mt][ng][r],
                                       fmaf(stat[128 + m_loc], __ldg(&g_s1[n_glb]), __ldg(&g_s2[n_glb])));
                        sbuf[n_loc * 128 + m_loc] = v;
                    }
        }
        __syncthreads();
#pragma unroll
        for (int r = 0; r < 48; r++) {
            int e  = r * 256 + tid;
            int nl = e >> 7;
            int ml = e & 127;
            int n  = h * 96 + nl;
            out[(size_t)(b * 192 + n) * 16384 + sp0 + ml] = sbuf[e];
        }
        if (h == 0) __syncthreads();
    }
}

// ---------------- launch ----------------
extern "C" void kernel_launch(void* const* d_in, const int* in_sizes, int n_in,
                              void* d_out, int out_size) {
    const float* x     = (const float*)d_in[0];
    const float* gamma = (const float*)d_in[1];
    const float* beta  = (const float*)d_in[2];
    const float* w_red = (const float*)d_in[3];
    float* out = (float*)d_out;

    cudaFuncSetAttribute(k_main, cudaFuncAttributeMaxDynamicSharedMemorySize, SMEM_TOTAL);

    k_prep<<<768, 256>>>(gamma, beta, w_red);
    k_main<<<256, 256, SMEM_TOTAL>>>(x, out);
}

// round 11
// speedup vs baseline: 1.8208x; 1.3115x over previous
#include <cuda_runtime.h>
#include <cuda_fp16.h>
#include <cstdint>

// ============================================================================
// helpers
// ============================================================================
__device__ __forceinline__ uint32_t smem_u32(const void* p) {
    uint32_t a;
    asm("{ .reg .u64 t; cvta.to.shared.u64 t, %1; cvt.u32.u64 %0, t; }" : "=r"(a) : "l"(p));
    return a;
}
__host__ __device__ __forceinline__ uint32_t swz128(uint32_t off) {
    return off ^ ((off >> 3) & 0x70);
}
__device__ __forceinline__ void ldsm4(uint32_t r[4], uint32_t addr) {
    asm volatile("ldmatrix.sync.aligned.m8n8.x4.shared.b16 {%0,%1,%2,%3}, [%4];"
                 : "=r"(r[0]), "=r"(r[1]), "=r"(r[2]), "=r"(r[3]) : "r"(addr));
}
__device__ __forceinline__ void mma16816(float d[4], const uint32_t a[4], uint32_t b0, uint32_t b1) {
    asm volatile("mma.sync.aligned.m16n8k16.row.col.f32.f16.f16.f32 "
                 "{%0,%1,%2,%3}, {%4,%5,%6,%7}, {%8,%9}, {%0,%1,%2,%3};"
                 : "+f"(d[0]), "+f"(d[1]), "+f"(d[2]), "+f"(d[3])
                 : "r"(a[0]), "r"(a[1]), "r"(a[2]), "r"(a[3]), "r"(b0), "r"(b1));
}
__device__ __forceinline__ void cpa16(uint32_t dst, const void* src) {
    asm volatile("cp.async.cg.shared.global [%0], [%1], 16;" :: "r"(dst), "l"(src));
}
#define CP_COMMIT() asm volatile("cp.async.commit_group;" ::: "memory")
#define CP_WAIT0()  asm volatile("cp.async.wait_group 0;" ::: "memory")

// ============================================================================
// smem layout (per CTA 82,944 B; 2 CTAs/SM)
// ============================================================================
static constexpr int SMEM_A0   = 0;        // 16 KB: A_hi 128x64 fp16, SW128 rows (buf 0)
static constexpr int SMEM_A1   = 16384;    // 16 KB: A buf 1
static constexpr int SMEM_B0   = 32768;    // 24 KB: B_hi buffer 0
static constexpr int SMEM_B1   = 57344;    // 24 KB: B_hi buffer 1
static constexpr int OFF_PSUM  = 32768;    // reuse B0 after compute
static constexpr int OFF_PSQ   = 36864;
static constexpr int OFF_STAT  = 81920;    // 1 KB
static constexpr int SMEM_TOTAL = 82944;

// ---------------- device scratch ----------------
__device__ float  g_s1[192];
__device__ float  g_s2[192];
__device__ float4 g_Bh[12 * 1536];   // 12 chunks x 24KB, pre-swizzled tile layout (fp16 hi)

// ---------------- prep kernel: B plane + s1/s2 ----------------
__global__ void k_prep(const float* __restrict__ gamma, const float* __restrict__ beta,
                       const float* __restrict__ w) {
    if (blockIdx.x < 576) {
        int t = blockIdx.x * 256 + threadIdx.x;
        int k = t / 192;       // original k = p*96 + c
        int n = t % 192;
        int p = k / 96, c = k % 96;
        float val = gamma[k] * w[k * 192 + n];
        int chunk = c >> 3;
        int kl = (c & 7) * 8 + p;              // k-hat within chunk
        uint32_t off = swz128((uint32_t)(n * 128 + kl * 2));
        *(__half*)((unsigned char*)g_Bh + chunk * 24576 + off) = __float2half_rn(val);
    } else {
        int n = blockIdx.x - 576;
        __shared__ float s1s[256], s2s[256];
        float s1 = 0.f, s2 = 0.f;
        for (int k = threadIdx.x; k < 768; k += 256) {
            float wv = w[k * 192 + n];
            s1 += gamma[k] * wv;
            s2 += beta[k] * wv;
        }
        s1s[threadIdx.x] = s1; s2s[threadIdx.x] = s2;
        __syncthreads();
        for (int off = 128; off > 0; off >>= 1) {
            if (threadIdx.x < off) { s1s[threadIdx.x] += s1s[threadIdx.x + off]; s2s[threadIdx.x] += s2s[threadIdx.x + off]; }
            __syncthreads();
        }
        if (threadIdx.x == 0) { g_s1[n] = s1s[0]; g_s2[n] = s2s[0]; }
    }
}

// ---------------- main fused kernel ----------------
__global__ void __launch_bounds__(256, 2) k_main(const float* __restrict__ x,
                                                 float* __restrict__ out) {
    extern __shared__ unsigned char smem[];
    const uint32_t sb  = smem_u32(smem);
    const int tid  = threadIdx.x;
    const int lane = tid & 31;
    const int wrp  = tid >> 5;
    const int wm   = wrp & 3;       // M quadrant (32 rows)
    const int wn   = wrp >> 2;      // N half (96 cols)

    // block coords: 128 consecutive m
    const int m0 = blockIdx.x * 128;
    const int b  = m0 >> 14;
    const int d  = (m0 >> 10) & 15;
    const int h0 = (m0 >> 5) & 31;     // multiple of 4
    const int idx = tid >> 5;          // c_local 0..7 (loader role)
    const int w   = tid & 31;

    const float2* x2 = (const float2*)x;
    const size_t baseIdx = ((size_t)(b * 96 + idx) * 32 + 2 * d) * 2048 + (size_t)(2 * h0) * 32 + w;

    // ldmatrix lane address components
    const int g  = lane >> 3, rl = lane & 7;
    const int aRowLane = ((g & 1) << 3) + rl;
    const int aKLane   = (g >> 1) << 4;
    const int bRowLane = ((g >> 1) << 3) + rl;
    const int bKLane   = (g & 1) << 4;

    float acc[2][12][4];
#pragma unroll
    for (int mt = 0; mt < 2; mt++)
#pragma unroll
        for (int ng = 0; ng < 12; ng++)
#pragma unroll
            for (int r = 0; r < 4; r++) acc[mt][ng][r] = 0.f;

    float sA[4] = {0.f, 0.f, 0.f, 0.f};
    float sQ[4] = {0.f, 0.f, 0.f, 0.f};

    float2 aPf[16];
    // ---- prologue: prefetch A chunk 0 into regs; stream B(0) via cp.async ----
#pragma unroll
    for (int i = 0; i < 16; i++)
        aPf[i] = x2[baseIdx + (size_t)((i >> 3) * 2048 + ((i >> 1) & 3) * 64 + (i & 1) * 32)];
    {
        const float4* bsrc = g_Bh + tid;
#pragma unroll
        for (int j = 0; j < 6; j++)
            cpa16(sb + SMEM_B0 + (uint32_t)(j * 256 + tid) * 16, bsrc + j * 256);
        CP_COMMIT();
    }

    for (int t = 0; t < 12; t++) {
        // ---- convert A(t) from regs into bufA[t&1] (other warps may still be
        //      finishing compute(t-1) on the other buffer) ----
        const uint32_t abuf = sb + (t & 1 ? SMEM_A1 : SMEM_A0);
#pragma unroll
        for (int i = 0; i < 16; i++) {
            float2 v = aPf[i];
            const int dz = i >> 3, hout = (i >> 1) & 3, hy = i & 1;
            const int kl = idx * 8 + dz * 4 + hy * 2;
            const int ml = hout * 32 + w;
            __half2 hi2 = __float22half2_rn(v);
            uint32_t off = swz128((uint32_t)(ml * 128 + kl * 2));
            *(uint32_t*)(abuf + off - sb + (size_t)smem) = *(uint32_t*)&hi2;
            sA[hout] += v.x + v.y;
            sQ[hout] = fmaf(v.x, v.x, fmaf(v.y, v.y, sQ[hout]));
        }
        CP_WAIT0();            // B(t) staged
        __syncthreads();       // STS visible; all warps done compute(t-1)

        // ---- stream B(t+1); prefetch A(t+1) into regs ----
        if (t < 11) {
            const float4* bsrc = g_Bh + (size_t)(t + 1) * 1536 + tid;
            uint32_t bdst = sb + ((t + 1) & 1 ? SMEM_B1 : SMEM_B0);
#pragma unroll
            for (int j = 0; j < 6; j++)
                cpa16(bdst + (uint32_t)(j * 256 + tid) * 16, bsrc + j * 256);
            CP_COMMIT();
            const size_t cb = baseIdx + (size_t)(t + 1) * 524288;
#pragma unroll
            for (int i = 0; i < 16; i++)
                aPf[i] = x2[cb + (size_t)((i >> 3) * 2048 + ((i >> 1) & 3) * 64 + (i & 1) * 32)];
        }

        // ---- compute: 4 k16-steps, single fp16 term ----
        const uint32_t bbase = sb + (t & 1 ? SMEM_B1 : SMEM_B0);
#pragma unroll
        for (int ks = 0; ks < 4; ks++) {
            uint32_t ahi[2][4];
#pragma unroll
            for (int mt = 0; mt < 2; mt++) {
                uint32_t rowoff = (uint32_t)((wm * 32 + mt * 16 + aRowLane) * 128 + ks * 32 + aKLane);
                ldsm4(ahi[mt], abuf + swz128(rowoff));
            }
#pragma unroll
            for (int ng2 = 0; ng2 < 6; ng2++) {
                uint32_t boff = (uint32_t)((wn * 96 + ng2 * 16 + bRowLane) * 128 + ks * 32 + bKLane);
                uint32_t bb[4];
                ldsm4(bb, bbase + swz128(boff));
                mma16816(acc[0][2 * ng2],     ahi[0], bb[0], bb[1]);
                mma16816(acc[1][2 * ng2],     ahi[1], bb[0], bb[1]);
                mma16816(acc[0][2 * ng2 + 1], ahi[0], bb[2], bb[3]);
                mma16816(acc[1][2 * ng2 + 1], ahi[1], bb[2], bb[3]);
            }
        }
    }
    __syncthreads();

    // ---- LayerNorm stats reduce ----
    float* psum = (float*)(smem + OFF_PSUM);
    float* psq  = (float*)(smem + OFF_PSQ);
#pragma unroll
    for (int hout = 0; hout < 4; hout++) {
        psum[idx * 128 + hout * 32 + w] = sA[hout];
        psq[idx * 128 + hout * 32 + w]  = sQ[hout];
    }
    __syncthreads();
    float* stat = (float*)(smem + OFF_STAT);
    if (tid < 128) {
        float S = 0.f, Q = 0.f;
#pragma unroll
        for (int r = 0; r < 8; r++) { S += psum[r * 128 + tid]; Q += psq[r * 128 + tid]; }
        float mu  = S * (1.0f / 768.0f);
        float var = Q * (1.0f / 768.0f) - mu * mu;
        float rs  = rsqrtf(var + 1e-5f);
        stat[tid]       = rs;
        stat[128 + tid] = -rs * mu;
    }
    __syncthreads();

    // ---- epilogue: LN affine + transposed writeback (two n-halves of 96) ----
    float* sbuf = (float*)smem;   // 96 x 128 floats = 48 KB (overlaps tiles)
    const int sp0 = (m0 & 16383);
    for (int h = 0; h < 2; h++) {
        if (wn == h) {
#pragma unroll
            for (int mt = 0; mt < 2; mt++)
#pragma unroll
                for (int ng = 0; ng < 12; ng++)
#pragma unroll
                    for (int r = 0; r < 4; r++) {
                        int m_loc = wm * 32 + mt * 16 + (lane >> 2) + ((r >> 1) << 3);
                        int n_loc = ng * 8 + ((lane & 3) << 1) + (r & 1);
                        int n_glb = h * 96 + n_loc;
                        float v = fmaf(stat[m_loc], acc[mt][ng][r],
                                       fmaf(stat[128 + m_loc], __ldg(&g_s1[n_glb]), __ldg(&g_s2[n_glb])));
                        sbuf[n_loc * 128 + m_loc] = v;
                    }
        }
        __syncthreads();
#pragma unroll
        for (int r = 0; r < 48; r++) {
            int e  = r * 256 + tid;
            int nl = e >> 7;
            int ml = e & 127;
            int n  = h * 96 + nl;
            out[(size_t)(b * 192 + n) * 16384 + sp0 + ml] = sbuf[e];
        }
        if (h == 0) __syncthreads();
    }
}

// ---------------- launch ----------------
extern "C" void kernel_launch(void* const* d_in, const int* in_sizes, int n_in,
                              void* d_out, int out_size) {
    const float* x     = (const float*)d_in[0];
    const float* gamma = (const float*)d_in[1];
    const float* beta  = (const float*)d_in[2];
    const float* w_red = (const float*)d_in[3];
    float* out = (float*)d_out;

    cudaFuncSetAttribute(k_main, cudaFuncAttributeMaxDynamicSharedMemorySize, SMEM_TOTAL);

    k_prep<<<768, 256>>>(gamma, beta, w_red);
    k_main<<<256, 256, SMEM_TOTAL>>>(x, out);
}

// round 13
// speedup vs baseline: 2.2729x; 1.2483x over previous
#include <cuda_runtime.h>
#include <cuda_fp16.h>
#include <cstdint>

// ============================================================================
// helpers
// ============================================================================
__device__ __forceinline__ uint32_t smem_u32(const void* p) {
    uint32_t a;
    asm("{ .reg .u64 t; cvta.to.shared.u64 t, %1; cvt.u32.u64 %0, t; }" : "=r"(a) : "l"(p));
    return a;
}
__host__ __device__ __forceinline__ uint32_t swz128(uint32_t off) {
    return off ^ ((off >> 3) & 0x70);
}
__device__ __forceinline__ void ldsm4(uint32_t r[4], uint32_t addr) {
    asm volatile("ldmatrix.sync.aligned.m8n8.x4.shared.b16 {%0,%1,%2,%3}, [%4];"
                 : "=r"(r[0]), "=r"(r[1]), "=r"(r[2]), "=r"(r[3]) : "r"(addr));
}
__device__ __forceinline__ void mma16816(float d[4], const uint32_t a[4], uint32_t b0, uint32_t b1) {
    asm volatile("mma.sync.aligned.m16n8k16.row.col.f32.f16.f16.f32 "
                 "{%0,%1,%2,%3}, {%4,%5,%6,%7}, {%8,%9}, {%0,%1,%2,%3};"
                 : "+f"(d[0]), "+f"(d[1]), "+f"(d[2]), "+f"(d[3])
                 : "r"(a[0]), "r"(a[1]), "r"(a[2]), "r"(a[3]), "r"(b0), "r"(b1));
}
__device__ __forceinline__ void cpa16(uint32_t dst, const void* src) {
    asm volatile("cp.async.cg.shared.global [%0], [%1], 16;" :: "r"(dst), "l"(src));
}
#define CP_COMMIT() asm volatile("cp.async.commit_group;" ::: "memory")
#define CP_WAIT0()  asm volatile("cp.async.wait_group 0;" ::: "memory")

// ============================================================================
// smem layout (per CTA 82,944 B; 2 CTAs/SM)
// ============================================================================
static constexpr int SMEM_A0   = 0;        // 16 KB: A_hi 128x64 fp16, SW128 rows (buf 0)
static constexpr int SMEM_A1   = 16384;    // 16 KB: A buf 1
static constexpr int SMEM_B0   = 32768;    // 24 KB: B_hi buffer 0
static constexpr int SMEM_B1   = 57344;    // 24 KB: B_hi buffer 1
static constexpr int OFF_PSUM  = 32768;    // reuse B0 after compute
static constexpr int OFF_PSQ   = 36864;
static constexpr int OFF_STAT  = 81920;    // 1 KB
static constexpr int SMEM_TOTAL = 82944;

// ---------------- device scratch ----------------
__device__ float  g_s1[192];
__device__ float  g_s2[192];
__device__ float4 g_Bh[12 * 1536];   // 12 chunks x 24KB, pre-swizzled tile layout (fp16 hi)

// ---------------- prep kernel: B plane + s1/s2 ----------------
__global__ void k_prep(const float* __restrict__ gamma, const float* __restrict__ beta,
                       const float* __restrict__ w) {
    if (blockIdx.x < 576) {
        int t = blockIdx.x * 256 + threadIdx.x;
        int k = t / 192;       // original k = p*96 + c
        int n = t % 192;
        int p = k / 96, c = k % 96;
        float val = gamma[k] * w[k * 192 + n];
        int chunk = c >> 3;
        int kl = (c & 7) * 8 + p;              // k-hat within chunk
        uint32_t off = swz128((uint32_t)(n * 128 + kl * 2));
        *(__half*)((unsigned char*)g_Bh + chunk * 24576 + off) = __float2half_rn(val);
    } else {
        int n = blockIdx.x - 576;
        __shared__ float s1s[256], s2s[256];
        float s1 = 0.f, s2 = 0.f;
        for (int k = threadIdx.x; k < 768; k += 256) {
            float wv = w[k * 192 + n];
            s1 += gamma[k] * wv;
            s2 += beta[k] * wv;
        }
        s1s[threadIdx.x] = s1; s2s[threadIdx.x] = s2;
        __syncthreads();
        for (int off = 128; off > 0; off >>= 1) {
            if (threadIdx.x < off) { s1s[threadIdx.x] += s1s[threadIdx.x + off]; s2s[threadIdx.x] += s2s[threadIdx.x + off]; }
            __syncthreads();
        }
        if (threadIdx.x == 0) { g_s1[n] = s1s[0]; g_s2[n] = s2s[0]; }
    }
}

// ---------------- main fused kernel ----------------
__global__ void __launch_bounds__(256, 2) k_main(const float* __restrict__ x,
                                                 float* __restrict__ out) {
    extern __shared__ unsigned char smem[];
    const uint32_t sb  = smem_u32(smem);
    const int tid  = threadIdx.x;
    const int lane = tid & 31;
    const int wrp  = tid >> 5;
    const int wm   = wrp & 3;       // M quadrant (32 rows)
    const int wn   = wrp >> 2;      // N half (96 cols)

    // block coords: 128 consecutive m
    const int m0 = blockIdx.x * 128;
    const int b  = m0 >> 14;
    const int d  = (m0 >> 10) & 15;
    const int h0 = (m0 >> 5) & 31;     // multiple of 4
    const int idx = tid >> 5;          // c_local 0..7 (loader role)
    const int w   = tid & 31;

    const float2* x2 = (const float2*)x;
    const size_t baseIdx = ((size_t)(b * 96 + idx) * 32 + 2 * d) * 2048 + (size_t)(2 * h0) * 32 + w;

    // ldmatrix lane address components
    const int g  = lane >> 3, rl = lane & 7;
    const int aRowLane = ((g & 1) << 3) + rl;
    const int aKLane   = (g >> 1) << 4;
    const int bRowLane = ((g >> 1) << 3) + rl;
    const int bKLane   = (g & 1) << 4;

    float acc[2][12][4];
#pragma unroll
    for (int mt = 0; mt < 2; mt++)
#pragma unroll
        for (int ng = 0; ng < 12; ng++)
#pragma unroll
            for (int r = 0; r < 4; r++) acc[mt][ng][r] = 0.f;

    float sA[4] = {0.f, 0.f, 0.f, 0.f};
    float sQ[4] = {0.f, 0.f, 0.f, 0.f};

    uint32_t aPk[16];   // packed fp16x2, converted at load time

    // ---- prologue: stream B(0); load+convert A chunk 0 ----
    {
        const float4* bsrc = g_Bh + tid;
#pragma unroll
        for (int j = 0; j < 6; j++)
            cpa16(sb + SMEM_B0 + (uint32_t)(j * 256 + tid) * 16, bsrc + j * 256);
        CP_COMMIT();
    }
#pragma unroll
    for (int i = 0; i < 16; i++) {
        float2 v = x2[baseIdx + (size_t)((i >> 3) * 2048 + ((i >> 1) & 3) * 64 + (i & 1) * 32)];
        const int hout = (i >> 1) & 3;
        sA[hout] += v.x + v.y;
        sQ[hout] = fmaf(v.x, v.x, fmaf(v.y, v.y, sQ[hout]));
        __half2 h2 = __float22half2_rn(v);
        aPk[i] = *(uint32_t*)&h2;
    }

    for (int t = 0; t < 12; t++) {
        // ---- STS A(t): 4x STS.128, conflict-free phases ----
        unsigned char* abase = smem + (t & 1 ? SMEM_A1 : SMEM_A0);
#pragma unroll
        for (int hout = 0; hout < 4; hout++) {
            uint4 pk;
            pk.x = aPk[hout * 2];       // dz=0, hy=0
            pk.y = aPk[hout * 2 + 1];   // dz=0, hy=1
            pk.z = aPk[hout * 2 + 8];   // dz=1, hy=0
            pk.w = aPk[hout * 2 + 9];   // dz=1, hy=1
            uint32_t off = swz128((uint32_t)((hout * 32 + w) * 128 + idx * 16));
            *(uint4*)(abase + off) = pk;
        }
        CP_WAIT0();            // B(t) staged
        __syncthreads();       // STS visible; all warps done compute(t-1)

        // ---- stream B(t+1); load+convert A(t+1) (stats at load) ----
        if (t < 11) {
            const float4* bsrc = g_Bh + (size_t)(t + 1) * 1536 + tid;
            uint32_t bdst = sb + ((t + 1) & 1 ? SMEM_B1 : SMEM_B0);
#pragma unroll
            for (int j = 0; j < 6; j++)
                cpa16(bdst + (uint32_t)(j * 256 + tid) * 16, bsrc + j * 256);
            CP_COMMIT();
            const size_t cb = baseIdx + (size_t)(t + 1) * 524288;
#pragma unroll
            for (int i = 0; i < 16; i++) {
                float2 v = x2[cb + (size_t)((i >> 3) * 2048 + ((i >> 1) & 3) * 64 + (i & 1) * 32)];
                const int hout = (i >> 1) & 3;
                sA[hout] += v.x + v.y;
                sQ[hout] = fmaf(v.x, v.x, fmaf(v.y, v.y, sQ[hout]));
                __half2 h2 = __float22half2_rn(v);
                aPk[i] = *(uint32_t*)&h2;
            }
        }

        // ---- compute: 4 k16-steps, single fp16 term ----
        const uint32_t abuf  = sb + (t & 1 ? SMEM_A1 : SMEM_A0);
        const uint32_t bbase = sb + (t & 1 ? SMEM_B1 : SMEM_B0);
#pragma unroll
        for (int ks = 0; ks < 4; ks++) {
            uint32_t ahi[2][4];
#pragma unroll
            for (int mt = 0; mt < 2; mt++) {
                uint32_t rowoff = (uint32_t)((wm * 32 + mt * 16 + aRowLane) * 128 + ks * 32 + aKLane);
                ldsm4(ahi[mt], abuf + swz128(rowoff));
            }
#pragma unroll
            for (int ng2 = 0; ng2 < 6; ng2++) {
                uint32_t boff = (uint32_t)((wn * 96 + ng2 * 16 + bRowLane) * 128 + ks * 32 + bKLane);
                uint32_t bb[4];
                ldsm4(bb, bbase + swz128(boff));
                mma16816(acc[0][2 * ng2],     ahi[0], bb[0], bb[1]);
                mma16816(acc[1][2 * ng2],     ahi[1], bb[0], bb[1]);
                mma16816(acc[0][2 * ng2 + 1], ahi[0], bb[2], bb[3]);
                mma16816(acc[1][2 * ng2 + 1], ahi[1], bb[2], bb[3]);
            }
        }
    }
    __syncthreads();

    // ---- LayerNorm stats reduce ----
    float* psum = (float*)(smem + OFF_PSUM);
    float* psq  = (float*)(smem + OFF_PSQ);
#pragma unroll
    for (int hout = 0; hout < 4; hout++) {
        psum[idx * 128 + hout * 32 + w] = sA[hout];
        psq[idx * 128 + hout * 32 + w]  = sQ[hout];
    }
    __syncthreads();
    float* stat = (float*)(smem + OFF_STAT);
    if (tid < 128) {
        float S = 0.f, Q = 0.f;
#pragma unroll
        for (int r = 0; r < 8; r++) { S += psum[r * 128 + tid]; Q += psq[r * 128 + tid]; }
        float mu  = S * (1.0f / 768.0f);
        float var = Q * (1.0f / 768.0f) - mu * mu;
        float rs  = rsqrtf(var + 1e-5f);
        stat[tid]       = rs;
        stat[128 + tid] = -rs * mu;
    }
    __syncthreads();

    // ---- epilogue: LN affine + transposed writeback (two n-halves of 96) ----
    float* sbuf = (float*)smem;   // 96 x 128 floats = 48 KB (overlaps tiles)
    const int sp0 = (m0 & 16383);
    for (int h = 0; h < 2; h++) {
        if (wn == h) {
#pragma unroll
            for (int mt = 0; mt < 2; mt++)
#pragma unroll
                for (int ng = 0; ng < 12; ng++)
#pragma unroll
                    for (int r = 0; r < 4; r++) {
                        int m_loc = wm * 32 + mt * 16 + (lane >> 2) + ((r >> 1) << 3);
                        int n_loc = ng * 8 + ((lane & 3) << 1) + (r & 1);
                        int n_glb = h * 96 + n_loc;
                        float v = fmaf(stat[m_loc], acc[mt][ng][r],
                                       fmaf(stat[128 + m_loc], __ldg(&g_s1[n_glb]), __ldg(&g_s2[n_glb])));
                        sbuf[n_loc * 128 + m_loc] = v;
                    }
        }
        __syncthreads();
#pragma unroll
        for (int r = 0; r < 48; r++) {
            int e  = r * 256 + tid;
            int nl = e >> 7;
            int ml = e & 127;
            int n  = h * 96 + nl;
            out[(size_t)(b * 192 + n) * 16384 + sp0 + ml] = sbuf[e];
        }
        if (h == 0) __syncthreads();
    }
}

// ---------------- launch ----------------
extern "C" void kernel_launch(void* const* d_in, const int* in_sizes, int n_in,
                              void* d_out, int out_size) {
    const float* x     = (const float*)d_in[0];
    const float* gamma = (const float*)d_in[1];
    const float* beta  = (const float*)d_in[2];
    const float* w_red = (const float*)d_in[3];
    float* out = (float*)d_out;

    cudaFuncSetAttribute(k_main, cudaFuncAttributeMaxDynamicSharedMemorySize, SMEM_TOTAL);

    k_prep<<<768, 256>>>(gamma, beta, w_red);
    k_main<<<256, 256, SMEM_TOTAL>>>(x, out);
}